// round 11
// baseline (speedup 1.0000x reference)
#include <cuda_runtime.h>
#include <math.h>

#define NB 2
#define NN 4096
#define MM 512
#define KK 50
#define EPSc 1e-5

typedef unsigned long long u64;

// ---------------- f32x2 packed helpers ----------------
__device__ __forceinline__ u64 pk2(float lo, float hi){
    u64 d;
    asm("mov.b64 %0, {%1, %2};" : "=l"(d)
        : "r"(__float_as_uint(lo)), "r"(__float_as_uint(hi)));
    return d;
}
__device__ __forceinline__ void upk2(float& lo, float& hi, u64 d){
    unsigned a, b;
    asm("mov.b64 {%0, %1}, %2;" : "=r"(a), "=r"(b) : "l"(d));
    lo = __uint_as_float(a); hi = __uint_as_float(b);
}
__device__ __forceinline__ u64 fma2(u64 a, u64 b, u64 c){
    u64 d;
    asm("fma.rn.f32x2 %0, %1, %2, %3;" : "=l"(d) : "l"(a), "l"(b), "l"(c));
    return d;
}
__device__ __forceinline__ u64 add2(u64 a, u64 b){
    u64 d;
    asm("add.rn.f32x2 %0, %1, %2;" : "=l"(d) : "l"(a), "l"(b));
    return d;
}
__device__ __forceinline__ u64 sub2(u64 a, u64 b){
    u64 d;
    asm("sub.rn.f32x2 %0, %1, %2;" : "=l"(d) : "l"(a), "l"(b));
    return d;
}
__device__ __forceinline__ float hsum2(u64 a){
    float lo, hi; upk2(lo, hi, a); return lo + hi;
}
__device__ __forceinline__ u64 shflmin64(u64 v, int off){
    unsigned lo = (unsigned)v, hi = (unsigned)(v >> 32);
    unsigned olo = __shfl_down_sync(0xffffffffu, lo, off);
    unsigned ohi = __shfl_down_sync(0xffffffffu, hi, off);
    u64 o = ((u64)ohi << 32) | olo;
    return o < v ? o : v;
}

// ---------------- scratch layout (floats) ----------------
#define F_XP3   0
#define F_XGP3  (F_XP3+NB*NN*3)
#define F_X1    (F_XGP3+NB*MM*3)
#define F_X2    (F_X1+NB*NN*64)
#define F_X3    (F_X2+NB*NN*64)
#define F_X1G   (F_X3+NB*NN*64)
#define F_X2G   (F_X1G+NB*MM*64)
#define F_X3G   (F_X2G+NB*MM*64)
#define F_P     (F_X3G+NB*MM*64)
#define F_R     (F_P+NB*NN*64)
#define F_Q     (F_R+NB*NN*64)
#define F_GNRM  (F_Q+NB*MM*64)
#define F_MAXB  (F_GNRM+NB*MM)
#define F_Y7    (F_MAXB+NB*NN*64)
#define F_Y8    (F_Y7+NB*NN*128)
#define F_W6P   (F_Y8+NB*NN*64)
#define F_W7P   (F_W6P+96*512*2)
#define F_W8P   (F_W7P+96*128*2)
#define F_W9P   (F_W8P+64*64*2)
#define F_W2T   (F_W9P+32*128*2)
#define F_W4T   (F_W2T+64*64)
#define F_C7    (F_W4T+64*64)
#define F_SC0   (F_C7+NB*128)
#define F_BI0   (F_SC0+512)
#define F_SC1   (F_BI0+512)
#define F_BI1   (F_SC1+512)
#define F_QS    (F_BI1+512)
#define F_QS2   (F_QS+NB*MM*64)
#define F_QM    (F_QS2+NB*MM*64)
#define F_TOT   (F_QM+NB*MM*64)

__device__ float g_f[F_TOT];
__device__ double g_d[2048];
__device__ unsigned long long g_near0[NB*NN];
__device__ unsigned long long g_near1[NB*NN];
__device__ unsigned long long g_near2[NB*NN];
__device__ int g_nbr[NB*MM*KK];
__device__ int g_cnt0[NB*MM];
__device__ int g_cnt1[NB*MM];
__device__ int g_offs[NB*MM];
__device__ int g_woffs[NB*MM];
__device__ int g_order[NB*NN];
__device__ unsigned g_max6[NB*512];

__device__ __forceinline__ unsigned long long packkey(float d, int m){
    unsigned u = __float_as_uint(d);
    u = (u & 0x80000000u) ? ~u : (u | 0x80000000u);
    return (((unsigned long long)u) << 32) | (unsigned)m;
}
__device__ __forceinline__ unsigned f2ord(float x){
    unsigned u = __float_as_uint(x);
    return (u & 0x80000000u) ? ~u : (u | 0x80000000u);
}
__device__ __forceinline__ float ord2f(unsigned u){
    return (u & 0x80000000u) ? __uint_as_float(u ^ 0x80000000u) : __uint_as_float(~u);
}
__device__ __forceinline__ float lrelu_f(float v){ return v >= 0.f ? v : 0.2f*v; }

// ---------------- setup: init + transpose + weight packing ----------------
__global__ void k_setup(const float* __restrict__ x, const float* __restrict__ xg,
                        const float* __restrict__ W2, const float* __restrict__ W4,
                        const float* __restrict__ W6, const float* __restrict__ W7,
                        const float* __restrict__ W8, const float* __restrict__ W9,
                        float* __restrict__ xp, float* __restrict__ xgp,
                        float* __restrict__ W2T, float* __restrict__ W4T,
                        float2* __restrict__ W6P, float2* __restrict__ W7P,
                        float2* __restrict__ W8P, float2* __restrict__ W9P){
    int stride = gridDim.x*blockDim.x;
    int i0 = blockIdx.x*blockDim.x + threadIdx.x;
    for (int i = i0; i < 2048; i += stride) g_d[i] = 0.0;
    for (int i = i0; i < NB*NN; i += stride){
        g_near0[i] = ~0ULL; g_near1[i] = ~0ULL; g_near2[i] = ~0ULL;
    }
    for (int i = i0; i < NB*MM; i += stride){ g_cnt0[i] = 0; g_cnt1[i] = 0; }
    for (int i = i0; i < NB*512; i += stride) g_max6[i] = 0u;
    for (int i = i0; i < NB*NN*3; i += stride){
        int b = i/(NN*3); int rem = i - b*NN*3; int n = rem/3; int c = rem - n*3;
        xp[i] = x[(b*3 + c)*NN + n];
    }
    for (int i = i0; i < NB*MM*3; i += stride){
        int b = i/(MM*3); int rem = i - b*MM*3; int m = rem/3; int c = rem - m*3;
        xgp[i] = xg[(b*3 + c)*MM + m];
    }
    for (int i = i0; i < 96*512; i += stride){
        int c2 = i/512, o = i - c2*512;
        W6P[i] = make_float2(W6[o*192 + 2*c2], W6[o*192 + 2*c2 + 1]);
    }
    for (int i = i0; i < 96*128; i += stride){
        int c2 = i/128, o = i - c2*128;
        W7P[i] = make_float2(W7[o*704 + 512 + 2*c2], W7[o*704 + 512 + 2*c2 + 1]);
    }
    for (int i = i0; i < 64*64; i += stride){
        int c2 = i >> 6, o = i & 63;
        W8P[i] = make_float2(W8[o*128 + 2*c2], W8[o*128 + 2*c2 + 1]);
    }
    for (int i = i0; i < 32*128; i += stride){
        int c2 = i >> 7, o = i & 127;
        W9P[i] = make_float2(W9[o*64 + 2*c2], W9[o*64 + 2*c2 + 1]);
    }
    for (int i = i0; i < 64*64; i += stride){
        int o = i >> 6, c = i & 63;
        W2T[c*64 + o] = W2[i];
        W4T[c*64 + o] = W4[i];
    }
}

// ---------------- fused stage prep: pqr + q + gn ----------------
template<int C>
__global__ void k_stageprep(const float* __restrict__ X, const float* __restrict__ G,
                            const float* __restrict__ W,
                            float* __restrict__ P, float* __restrict__ R,
                            float* __restrict__ Q, float* __restrict__ gn){
    const int BA = NB*NN*64/256;
    const int BB = NB*MM*64/256;
    int bid = blockIdx.x;
    if (bid < BA){
        int i = bid*256 + threadIdx.x;
        int o = i & 63; int pn = i >> 6;
        if (C == 3){
            const float* Xp = X + (size_t)pn*3;
            const float* Wo = W + (size_t)o*6;
            float p = 0.f, r = 0.f;
            #pragma unroll
            for (int c = 0; c < 3; c++){
                float xv = Xp[c]; float wl = Wo[c]; float wh = Wo[3 + c];
                p = fmaf(wh - wl, xv, p);
                r = fmaf(wl, xv, r);
            }
            P[i] = p; R[i] = r;
        } else {
            const u64* X2 = (const u64*)(X + (size_t)pn*64);
            const u64* WL = (const u64*)(W + (size_t)o*128);
            u64 pa = 0, pb = 0, ra = 0, rb = 0;
            #pragma unroll
            for (int c2 = 0; c2 < 32; c2 += 2){
                u64 xv0 = X2[c2], xv1 = X2[c2+1];
                u64 wl0 = WL[c2], wl1 = WL[c2+1];
                u64 wh0 = WL[32+c2], wh1 = WL[32+c2+1];
                pa = fma2(sub2(wh0, wl0), xv0, pa);
                ra = fma2(wl0, xv0, ra);
                pb = fma2(sub2(wh1, wl1), xv1, pb);
                rb = fma2(wl1, xv1, rb);
            }
            P[i] = hsum2(add2(pa, pb));
            R[i] = hsum2(add2(ra, rb));
        }
    } else if (bid < BA + BB){
        int i = (bid - BA)*256 + threadIdx.x;
        int o = i & 63; int pm = i >> 6;
        if (C == 3){
            const float* Gp = G + (size_t)pm*3;
            const float* Wo = W + (size_t)o*6;
            float q = 0.f;
            #pragma unroll
            for (int c = 0; c < 3; c++) q = fmaf(Wo[c], Gp[c], q);
            Q[i] = q;
        } else {
            const u64* G2 = (const u64*)(G + (size_t)pm*64);
            const u64* WL = (const u64*)(W + (size_t)o*128);
            u64 qa = 0, qb = 0;
            #pragma unroll
            for (int c2 = 0; c2 < 32; c2 += 2){
                qa = fma2(WL[c2], G2[c2], qa);
                qb = fma2(WL[c2+1], G2[c2+1], qb);
            }
            Q[i] = hsum2(add2(qa, qb));
        }
    } else {
        int i = (bid - BA - BB)*256 + threadIdx.x;
        if (i >= NB*MM) return;
        if (C == 3){
            const float* Gp = G + (size_t)i*3;
            gn[i] = Gp[0]*Gp[0] + Gp[1]*Gp[1] + Gp[2]*Gp[2];
        } else {
            const u64* G2 = (const u64*)(G + (size_t)i*64);
            u64 a = 0, b = 0;
            #pragma unroll
            for (int c2 = 0; c2 < 32; c2 += 2){
                a = fma2(G2[c2], G2[c2], a);
                b = fma2(G2[c2+1], G2[c2+1], b);
            }
            gn[i] = hsum2(add2(a, b));
        }
    }
}

// ---------------- fused graph: 50-NN (register top-k, exact keys) + per-cell qsum + nearest ----------------
template<int C>
__global__ void __launch_bounds__(128)
k_graph(const float* __restrict__ X, const float* __restrict__ G,
        const float* __restrict__ gn, const float* __restrict__ Q,
        float* __restrict__ QS, float* __restrict__ QS2, float* __restrict__ QM,
        unsigned long long* __restrict__ nearp){
    const int NBRB = NB*MM/4;
    __shared__ int snbr_s[4][KK];
    if (blockIdx.x < NBRB){
        int w = threadIdx.x >> 5, lane = threadIdx.x & 31;
        int cell = blockIdx.x*4 + w;
        int b = cell >> 9, m = cell & 511;
        const float* Gb = G + (size_t)b*MM*C;
        float cm[C];
        #pragma unroll
        for (int c = 0; c < C; c++) cm[c] = Gb[(size_t)m*C + c];
        float gm = gn[b*MM + m];
        u64 key[16];
        #pragma unroll
        for (int t = 0; t < 16; t++){
            int j = t*32 + lane;
            float dot = 0.f;
            if (C == 64){
                const float4* Gr = (const float4*)(Gb + (size_t)j*64);
                #pragma unroll
                for (int c4 = 0; c4 < 16; c4++){
                    float4 g = Gr[c4];
                    dot = fmaf(cm[4*c4],   g.x, dot);
                    dot = fmaf(cm[4*c4+1], g.y, dot);
                    dot = fmaf(cm[4*c4+2], g.z, dot);
                    dot = fmaf(cm[4*c4+3], g.w, dot);
                }
            } else {
                #pragma unroll
                for (int c = 0; c < C; c++) dot = fmaf(cm[c], Gb[(size_t)j*C + c], dot);
            }
            float d = gm + gn[b*MM + j] - 2.f*dot;
            key[t] = (j == m) ? (u64)j : ((((u64)f2ord(d)) << 32) | (unsigned)j);
        }
        int* nout = g_nbr + (size_t)cell*KK;
        for (int k = 0; k < KK; k++){
            u64 bk = key[0];
            #pragma unroll
            for (int t = 1; t < 16; t++) bk = min(bk, key[t]);
            bk = shflmin64(bk, 16);
            bk = shflmin64(bk, 8);
            bk = shflmin64(bk, 4);
            bk = shflmin64(bk, 2);
            bk = shflmin64(bk, 1);
            unsigned lo = __shfl_sync(0xffffffffu, (unsigned)bk, 0);
            int bj = (int)(lo & 511u);
            if (lane == 0){ nout[k] = bj; snbr_s[w][k] = bj; }
            if ((bj & 31) == lane) key[bj >> 5] = ~0ULL;
        }
        __syncwarp();
        // qsum for this cell: lane covers channels 2*lane, 2*lane+1
        u64 qs = 0, q2 = 0;
        float qmlo = -INFINITY, qmhi = -INFINITY;
        #pragma unroll 7
        for (int k = 1; k < KK; k++){
            int mk = snbr_s[w][k];
            u64 q = *(const u64*)(Q + ((size_t)(b*MM + mk))*64 + 2*lane);
            qs = add2(qs, q);
            q2 = fma2(q, q, q2);
            float lo2, hi2; upk2(lo2, hi2, q);
            qmlo = fmaxf(qmlo, lo2); qmhi = fmaxf(qmhi, hi2);
        }
        *(u64*)(QS  + (size_t)cell*64 + 2*lane) = qs;
        *(u64*)(QS2 + (size_t)cell*64 + 2*lane) = q2;
        *(u64*)(QM  + (size_t)cell*64 + 2*lane) = pk2(qmlo, qmhi);
    } else {
        int t = blockIdx.x - NBRB;
        if (C == 3){
            int bx = t & 31, by = (t >> 5) & 7, bz = t >> 8;
            int m0 = by*64;
            int n = bx*128 + threadIdx.x;
            __shared__ float sg[64*3];
            __shared__ float sgn[64];
            const float* Gb = G + ((size_t)bz*MM + m0)*3;
            for (int i = threadIdx.x; i < 64*3; i += 128) sg[i] = Gb[i];
            if (threadIdx.x < 64) sgn[threadIdx.x] = gn[bz*MM + m0 + threadIdx.x];
            __syncthreads();
            const float* Xp = X + ((size_t)bz*NN + n)*3;
            float x0 = Xp[0], x1 = Xp[1], x2 = Xp[2];
            float best = INFINITY; int bi = 0;
            for (int j = 0; j < 64; j++){
                float dot = x0*sg[j*3] + x1*sg[j*3+1] + x2*sg[j*3+2];
                float d = sgn[j] - 2.f*dot;
                if (d < best){ best = d; bi = m0 + j; }
            }
            atomicMin(&nearp[(size_t)bz*NN + n], packkey(best, bi));
        } else {
            int bx = t & 15, by = (t >> 4) & 7, bz = t >> 7;
            int m0 = by*64;
            int tid = threadIdx.x;
            int n0 = bx*256 + tid;
            __shared__ __align__(16) float sg[64*64];
            __shared__ float sgn[64];
            const float4* Gb4 = (const float4*)(G + ((size_t)bz*MM + m0)*64);
            for (int i = tid; i < 64*16; i += 128) ((float4*)sg)[i] = Gb4[i];
            if (tid < 64) sgn[tid] = gn[bz*MM + m0 + tid];
            __syncthreads();
            u64 xp0[32], xp1[32];
            const u64* X0 = (const u64*)(X + ((size_t)bz*NN + n0)*64);
            const u64* X1 = (const u64*)(X + ((size_t)bz*NN + n0 + 128)*64);
            #pragma unroll
            for (int c2 = 0; c2 < 32; c2++){ xp0[c2] = X0[c2]; xp1[c2] = X1[c2]; }
            float best0 = INFINITY, best1 = INFINITY; int bi0 = 0, bi1 = 0;
            for (int j = 0; j < 64; j++){
                const ulonglong2* g2 = (const ulonglong2*)(sg + j*64);
                u64 a0 = 0, a1 = 0, b0 = 0, b1 = 0;
                #pragma unroll
                for (int i = 0; i < 16; i++){
                    ulonglong2 tt = g2[i];
                    a0 = fma2(xp0[2*i],   tt.x, a0);
                    a1 = fma2(xp0[2*i+1], tt.y, a1);
                    b0 = fma2(xp1[2*i],   tt.x, b0);
                    b1 = fma2(xp1[2*i+1], tt.y, b1);
                }
                float gnj = sgn[j];
                float d0 = gnj - 2.f*hsum2(add2(a0, a1));
                float d1 = gnj - 2.f*hsum2(add2(b0, b1));
                if (d0 < best0){ best0 = d0; bi0 = m0 + j; }
                if (d1 < best1){ best1 = d1; bi1 = m0 + j; }
            }
            atomicMin(&nearp[(size_t)bz*NN + n0],       packkey(best0, bi0));
            atomicMin(&nearp[(size_t)bz*NN + n0 + 128], packkey(best1, bi1));
        }
    }
}

// ---------------- analytic BN stats of y_a over (n,k), fused hist ----------------
__global__ void k_ptstats(const float* __restrict__ P, const float* __restrict__ R,
                          const float* __restrict__ QS, const float* __restrict__ QS2,
                          const unsigned long long* __restrict__ nearp,
                          double* __restrict__ gsum, double* __restrict__ gsq,
                          int* __restrict__ cnt, int withhist){
    int tid = threadIdx.x; int slot = tid >> 6; int o = tid & 63;
    double s = 0.0, q = 0.0;
    for (int i = 0; i < 16; i++){
        int pn = blockIdx.x*64 + i*4 + slot;
        int b = pn >> 12;
        int nr = (int)(nearp[pn] & 0xFFFFFFFFu);
        double p  = P[(size_t)pn*64 + o];
        double r  = R[(size_t)pn*64 + o];
        double qs = QS[((size_t)(b*MM + nr))*64 + o];
        double q2 = QS2[((size_t)(b*MM + nr))*64 + o];
        s += 50.0*p + r + qs;
        q += 50.0*p*p + 2.0*p*(r + qs) + r*r + q2;
        if (withhist && o == 0) atomicAdd(&cnt[b*MM + nr], 1);
    }
    __shared__ double sS[256], sQ[256];
    sS[tid] = s; sQ[tid] = q;
    __syncthreads();
    if (tid < 64){
        s = sS[tid] + sS[tid+64] + sS[tid+128] + sS[tid+192];
        q = sQ[tid] + sQ[tid+64] + sQ[tid+128] + sQ[tid+192];
        atomicAdd(&gsum[tid], s);
        atomicAdd(&gsq[tid], q);
    }
}

// ---------------- scan + bnparams fused ----------------
__global__ void k_scanbn(const int* __restrict__ cnt,
                         const double* __restrict__ sum, const double* __restrict__ sq,
                         const float* __restrict__ gma, const float* __restrict__ bta,
                         float* __restrict__ sc, float* __restrict__ bi){
    if (blockIdx.x == 0){
        __shared__ int s[NB*MM];
        int tid = threadIdx.x;
        s[tid] = cnt[tid];
        __syncthreads();
        for (int off = 1; off < NB*MM; off <<= 1){
            int v = (tid >= off) ? s[tid-off] : 0;
            __syncthreads();
            s[tid] += v;
            __syncthreads();
        }
        int e = s[tid] - cnt[tid];
        g_offs[tid] = e; g_woffs[tid] = e;
    } else {
        int o = threadIdx.x;
        if (o >= 64) return;
        double mean = sum[o]/409600.0;
        double var = sq[o]/409600.0 - mean*mean;
        if (var < 0.0) var = 0.0;
        double s = (double)gma[o] / sqrt(var + (double)EPSc);
        sc[o] = (float)s;
        bi[o] = (float)((double)bta[o] - mean*s);
    }
}

__global__ void k_scatter(const unsigned long long* __restrict__ nearp){
    int pn = blockIdx.x*blockDim.x + threadIdx.x;
    if (pn >= NB*NN) return;
    int nr = (int)(nearp[pn] & 0xFFFFFFFFu);
    int pos = atomicAdd(&g_woffs[(pn >> 12)*MM + nr], 1);
    g_order[pos] = pn;
}

// ---------------- BN params (standalone) ----------------
__global__ void k_bnparams(const double* __restrict__ sum, const double* __restrict__ sq,
                           const float* __restrict__ gma, const float* __restrict__ bta,
                           int nch, double cnt, float* __restrict__ sc, float* __restrict__ bi){
    int o = threadIdx.x;
    if (o >= nch) return;
    double mean = sum[o]/cnt;
    double var = sq[o]/cnt - mean*mean;
    if (var < 0.0) var = 0.0;
    double s = (double)gma[o] / sqrt(var + (double)EPSc);
    sc[o] = (float)s;
    bi[o] = (float)((double)bta[o] - mean*s);
}

// ---------------- fused second edge-conv: 4 blocks per cell, k-chunks of 25 ----------------
__global__ void __launch_bounds__(128)
k_convb(const float* __restrict__ P, const float* __restrict__ R, const float* __restrict__ Q,
        const float* __restrict__ WT, const float* __restrict__ scA, const float* __restrict__ biA,
        const int* __restrict__ cnt, float* __restrict__ gmax,
        double* __restrict__ gsum, double* __restrict__ gsq){
    __shared__ float Qs[KK*64];
    __shared__ __align__(16) float2 hs[2][25][64];
    __shared__ int snbr[KK];
    int cell = blockIdx.x >> 2;
    int qsel = blockIdx.x & 3;
    int count0 = cnt[cell];
    if (count0 == 0) return;
    int q0 = (count0*qsel) >> 2;
    int q1 = (count0*(qsel+1)) >> 2;
    int count = q1 - q0;
    if (count <= 0) return;
    int start = g_offs[cell] + q0;
    int b = cell >> 9;
    int tid = threadIdx.x, half = tid >> 6, o = tid & 63;
    if (tid < KK) snbr[tid] = g_nbr[(size_t)cell*KK + tid];
    if (tid < 64) Qs[tid] = 0.f;
    __syncthreads();
    for (int idx = tid; idx < 49*64; idx += 128){
        int k = 1 + (idx >> 6), oo = idx & 63;
        Qs[k*64 + oo] = Q[((size_t)(b*MM + snbr[k]))*64 + oo];
    }
    u64 Wd[64];
    #pragma unroll
    for (int c = 0; c < 64; c++){ float w = WT[c*64 + o]; Wd[c] = pk2(w, w); }
    float sc = scA[o], bi = biA[o];
    __syncthreads();
    int barid = half + 1;
    double dsum = 0.0, dsq = 0.0;
    for (int pi = 0; pi < count; pi += 4){
        int iA = pi + 2*half, iB = iA + 1;
        bool vA = iA < count, vB = iB < count;
        int pA = g_order[start + (vA ? iA : 0)];
        int pB = g_order[start + (vB ? iB : 0)];
        float p0 = P[(size_t)pA*64 + o], r0 = R[(size_t)pA*64 + o];
        float p1 = P[(size_t)pB*64 + o], r1 = R[(size_t)pB*64 + o];
        float fsA = 0.f, fqA = 0.f, mxA = -INFINITY;
        float fsB = 0.f, fqB = 0.f, mxB = -INFINITY;
        for (int cc = 0; cc < 2; cc++){
            #pragma unroll
            for (int j = 0; j < 25; j++){
                int k = cc*25 + j;
                float q = Qs[k*64 + o];
                float v0 = (k == 0) ? (p0 + r0) : (p0 + q);
                float v1 = (k == 0) ? (p1 + r1) : (p1 + q);
                float h0 = lrelu_f(fmaf(v0, sc, bi));
                float h1 = lrelu_f(fmaf(v1, sc, bi));
                hs[half][j][o] = make_float2(h0, h1);
            }
            asm volatile("bar.sync %0, 64;" :: "r"(barid) : "memory");
            #pragma unroll 5
            for (int j = 0; j < 25; j++){
                const ulonglong2* h4 = (const ulonglong2*)hs[half][j];
                u64 a0 = 0, a1 = 0, a2 = 0, a3 = 0;
                #pragma unroll
                for (int c2 = 0; c2 < 32; c2 += 2){
                    ulonglong2 t0 = h4[c2];
                    ulonglong2 t1 = h4[c2+1];
                    a0 = fma2(Wd[2*c2],   t0.x, a0);
                    a1 = fma2(Wd[2*c2+1], t0.y, a1);
                    a2 = fma2(Wd[2*c2+2], t1.x, a2);
                    a3 = fma2(Wd[2*c2+3], t1.y, a3);
                }
                u64 s2 = add2(add2(a0, a1), add2(a2, a3));
                float yA, yB; upk2(yA, yB, s2);
                if (vA){ fsA += yA; fqA = fmaf(yA, yA, fqA); mxA = fmaxf(mxA, yA); }
                if (vB){ fsB += yB; fqB = fmaf(yB, yB, fqB); mxB = fmaxf(mxB, yB); }
            }
            asm volatile("bar.sync %0, 64;" :: "r"(barid) : "memory");
        }
        if (vA){ gmax[(size_t)pA*64 + o] = mxA; dsum += fsA; dsq += fqA; }
        if (vB){ gmax[(size_t)pB*64 + o] = mxB; dsum += fsB; dsq += fqB; }
    }
    atomicAdd(&gsum[o], dsum);
    atomicAdd(&gsq[o], dsq);
}

// ---------------- x = lrelu(bn(maxb)) + gather (fused) ----------------
__global__ void k_xg(const float* __restrict__ gmax, const float* __restrict__ sc,
                     const float* __restrict__ bi, const int* __restrict__ FPS,
                     float* __restrict__ X, float* __restrict__ XG){
    int i = blockIdx.x*blockDim.x + threadIdx.x;
    if (i < NB*NN*64){
        int o = i & 63;
        X[i] = lrelu_f(fmaf(gmax[i], sc[o], bi[o]));
    } else {
        int j = i - NB*NN*64;
        if (j >= NB*MM*64) return;
        int o = j & 63; int pm = j >> 6; int b = pm >> 9; int m = pm & 511;
        int n = FPS[b*MM + m];
        XG[j] = lrelu_f(fmaf(gmax[(((size_t)b*NN) + n)*64 + o], sc[o], bi[o]));
    }
}

// ---------------- stage3: x3 = lrelu(bn(P + max(R, QM[near]))) + gather ----------------
__global__ void k_x3g(const float* __restrict__ P, const float* __restrict__ R,
                      const float* __restrict__ QM,
                      const unsigned long long* __restrict__ nearp,
                      const float* __restrict__ sc, const float* __restrict__ bi,
                      const int* __restrict__ FPS,
                      float* __restrict__ X, float* __restrict__ XG){
    int i = blockIdx.x*blockDim.x + threadIdx.x;
    if (i < NB*NN*64){
        int o = i & 63; int pn = i >> 6; int b = pn >> 12;
        int nr = (int)(nearp[pn] & 0xFFFFFFFFu);
        float v = P[i] + fmaxf(R[i], QM[((size_t)(b*MM + nr))*64 + o]);
        X[i] = lrelu_f(fmaf(v, sc[o], bi[o]));
    } else {
        int j = i - NB*NN*64;
        if (j >= NB*MM*64) return;
        int o = j & 63; int pm = j >> 6; int b = pm >> 9; int m = pm & 511;
        int pn = b*NN + FPS[b*MM + m];
        int nr = (int)(nearp[pn] & 0xFFFFFFFFu);
        float v = P[(size_t)pn*64 + o] + fmaxf(R[(size_t)pn*64 + o], QM[((size_t)(b*MM + nr))*64 + o]);
        XG[j] = lrelu_f(fmaf(v, sc[o], bi[o]));
    }
}

// ---------------- y6 = W6 * [x1g;x2g;x3g], stats + per-(b,o) max (packed) ----------------
__global__ void k_y6stats(const float* __restrict__ x1g, const float* __restrict__ x2g,
                          const float* __restrict__ x3g, const float2* __restrict__ WP,
                          double* __restrict__ gsum, double* __restrict__ gsq){
    __shared__ __align__(16) float sF[16][192];
    int tid = threadIdx.x; int pm0 = blockIdx.x*16; int b = pm0 >> 9;
    for (int idx = tid; idx < 16*192; idx += 128){
        int p = idx/192, c = idx - p*192; int pm = pm0 + p;
        float v = (c < 64) ? x1g[(size_t)pm*64 + c]
                : (c < 128) ? x2g[(size_t)pm*64 + c - 64]
                            : x3g[(size_t)pm*64 + c - 128];
        sF[p][c] = v;
    }
    __syncthreads();
    int o = blockIdx.y*128 + tid;
    const u64* W2p = (const u64*)WP;
    double s = 0.0, q = 0.0; float mx = -INFINITY;
    for (int p0 = 0; p0 < 16; p0 += 4){
        const u64* f0 = (const u64*)sF[p0+0];
        const u64* f1 = (const u64*)sF[p0+1];
        const u64* f2 = (const u64*)sF[p0+2];
        const u64* f3 = (const u64*)sF[p0+3];
        u64 a0 = 0, a1 = 0, a2 = 0, a3 = 0;
        for (int c2 = 0; c2 < 96; c2++){
            u64 wp = W2p[c2*512 + o];
            a0 = fma2(wp, f0[c2], a0);
            a1 = fma2(wp, f1[c2], a1);
            a2 = fma2(wp, f2[c2], a2);
            a3 = fma2(wp, f3[c2], a3);
        }
        float y0 = hsum2(a0), y1 = hsum2(a1), y2 = hsum2(a2), y3 = hsum2(a3);
        s += (double)y0 + (double)y1 + (double)y2 + (double)y3;
        q += (double)y0*y0 + (double)y1*y1 + (double)y2*y2 + (double)y3*y3;
        mx = fmaxf(fmaxf(fmaxf(mx, y0), fmaxf(y1, y2)), y3);
    }
    atomicAdd(&gsum[o], s);
    atomicAdd(&gsq[o], q);
    atomicMax(&g_max6[b*512 + o], f2ord(mx));
}

// ---------------- c7[b,o] = W7[:, :512] . lrelu(bn6(y6max)) ----------------
__global__ void k_c7(const float* __restrict__ W7, const float* __restrict__ sc,
                     const float* __restrict__ bi, float* __restrict__ c7){
    int t = threadIdx.x; int b = t >> 7, o = t & 127;
    float acc = 0.f;
    for (int c = 0; c < 512; c++){
        float v = ord2f(g_max6[b*512 + c]);
        float h = fmaf(v, sc[c], bi[c]);
        h = (h >= 0.f) ? h : 0.2f*h;
        acc = fmaf(W7[(size_t)o*704 + c], h, acc);
    }
    c7[t] = acc;
}

// ---------------- y7 = c7 + W7[:,512:] * [x1;x2;x3], stats (packed) ----------------
__global__ void k_y7(const float* __restrict__ x1, const float* __restrict__ x2,
                     const float* __restrict__ x3, const float2* __restrict__ WP,
                     const float* __restrict__ c7, float* __restrict__ y7,
                     double* __restrict__ gsum, double* __restrict__ gsq){
    __shared__ __align__(16) float sF[16][192];
    int tid = threadIdx.x; int pn0 = blockIdx.x*16; int b = pn0 >> 12;
    for (int idx = tid; idx < 16*192; idx += 128){
        int p = idx/192, c = idx - p*192; int pn = pn0 + p;
        float v = (c < 64) ? x1[(size_t)pn*64 + c]
                : (c < 128) ? x2[(size_t)pn*64 + c - 64]
                            : x3[(size_t)pn*64 + c - 128];
        sF[p][c] = v;
    }
    __syncthreads();
    int o = tid;
    float ci = c7[b*128 + o];
    const u64* W2p = (const u64*)WP;
    double s = 0.0, q = 0.0;
    for (int p0 = 0; p0 < 16; p0 += 4){
        const u64* f0 = (const u64*)sF[p0+0];
        const u64* f1 = (const u64*)sF[p0+1];
        const u64* f2 = (const u64*)sF[p0+2];
        const u64* f3 = (const u64*)sF[p0+3];
        u64 a0 = 0, a1 = 0, a2 = 0, a3 = 0;
        for (int c2 = 0; c2 < 96; c2++){
            u64 wp = W2p[c2*128 + o];
            a0 = fma2(wp, f0[c2], a0);
            a1 = fma2(wp, f1[c2], a1);
            a2 = fma2(wp, f2[c2], a2);
            a3 = fma2(wp, f3[c2], a3);
        }
        float y0 = ci + hsum2(a0), y1 = ci + hsum2(a1);
        float y2 = ci + hsum2(a2), y3 = ci + hsum2(a3);
        y7[(size_t)(pn0+p0+0)*128 + o] = y0;
        y7[(size_t)(pn0+p0+1)*128 + o] = y1;
        y7[(size_t)(pn0+p0+2)*128 + o] = y2;
        y7[(size_t)(pn0+p0+3)*128 + o] = y3;
        s += (double)y0 + (double)y1 + (double)y2 + (double)y3;
        q += (double)y0*y0 + (double)y1*y1 + (double)y2*y2 + (double)y3*y3;
    }
    atomicAdd(&gsum[o], s);
    atomicAdd(&gsq[o], q);
}

// ---------------- y8 = W8 * lrelu(bn7(y7)), stats (packed) ----------------
__global__ void k_y8(const float* __restrict__ y7, const float2* __restrict__ WP,
                     const float* __restrict__ sc7, const float* __restrict__ bi7,
                     float* __restrict__ y8, double* __restrict__ gsum, double* __restrict__ gsq){
    __shared__ __align__(16) float sF[16][128];
    int tid = threadIdx.x; int pn0 = blockIdx.x*16;
    for (int idx = tid; idx < 16*128; idx += 64){
        int p = idx >> 7, c = idx & 127;
        float v = y7[(size_t)(pn0+p)*128 + c];
        float h = fmaf(v, sc7[c], bi7[c]);
        sF[p][c] = (h >= 0.f) ? h : 0.2f*h;
    }
    __syncthreads();
    int o = tid;
    const u64* W2p = (const u64*)WP;
    double s = 0.0, q = 0.0;
    for (int p0 = 0; p0 < 16; p0 += 4){
        const u64* f0 = (const u64*)sF[p0+0];
        const u64* f1 = (const u64*)sF[p0+1];
        const u64* f2 = (const u64*)sF[p0+2];
        const u64* f3 = (const u64*)sF[p0+3];
        u64 a0 = 0, a1 = 0, a2 = 0, a3 = 0;
        for (int c2 = 0; c2 < 64; c2++){
            u64 wp = W2p[c2*64 + o];
            a0 = fma2(wp, f0[c2], a0);
            a1 = fma2(wp, f1[c2], a1);
            a2 = fma2(wp, f2[c2], a2);
            a3 = fma2(wp, f3[c2], a3);
        }
        float y0 = hsum2(a0), y1 = hsum2(a1), y2 = hsum2(a2), y3 = hsum2(a3);
        y8[(size_t)(pn0+p0+0)*64 + o] = y0;
        y8[(size_t)(pn0+p0+1)*64 + o] = y1;
        y8[(size_t)(pn0+p0+2)*64 + o] = y2;
        y8[(size_t)(pn0+p0+3)*64 + o] = y3;
        s += (double)y0 + (double)y1 + (double)y2 + (double)y3;
        q += (double)y0*y0 + (double)y1*y1 + (double)y2*y2 + (double)y3*y3;
    }
    atomicAdd(&gsum[o], s);
    atomicAdd(&gsq[o], q);
}

// ---------------- out = W9 * lrelu(bn8(y8)) (packed) ----------------
__global__ void k_out(const float* __restrict__ y8, const float2* __restrict__ WP,
                      const float* __restrict__ sc8, const float* __restrict__ bi8,
                      float* __restrict__ out){
    __shared__ __align__(16) float sF[16][64];
    int tid = threadIdx.x; int pn0 = blockIdx.x*16;
    for (int idx = tid; idx < 16*64; idx += 128){
        int p = idx >> 6, c = idx & 63;
        float v = y8[(size_t)(pn0+p)*64 + c];
        float h = fmaf(v, sc8[c], bi8[c]);
        sF[p][c] = (h >= 0.f) ? h : 0.2f*h;
    }
    __syncthreads();
    int o = tid;
    const u64* W2p = (const u64*)WP;
    for (int p0 = 0; p0 < 16; p0 += 4){
        const u64* f0 = (const u64*)sF[p0+0];
        const u64* f1 = (const u64*)sF[p0+1];
        const u64* f2 = (const u64*)sF[p0+2];
        const u64* f3 = (const u64*)sF[p0+3];
        u64 a0 = 0, a1 = 0, a2 = 0, a3 = 0;
        for (int c2 = 0; c2 < 32; c2++){
            u64 wp = W2p[c2*128 + o];
            a0 = fma2(wp, f0[c2], a0);
            a1 = fma2(wp, f1[c2], a1);
            a2 = fma2(wp, f2[c2], a2);
            a3 = fma2(wp, f3[c2], a3);
        }
        out[(size_t)(pn0+p0+0)*128 + o] = hsum2(a0);
        out[(size_t)(pn0+p0+1)*128 + o] = hsum2(a1);
        out[(size_t)(pn0+p0+2)*128 + o] = hsum2(a2);
        out[(size_t)(pn0+p0+3)*128 + o] = hsum2(a3);
    }
}

// ---------------- host ----------------
extern "C" void kernel_launch(void* const* d_in, const int* in_sizes, int n_in,
                              void* d_out, int out_size){
    const float* x  = (const float*)d_in[0];
    const float* xg = (const float*)d_in[1];
    const int* FPS  = (const int*)d_in[2];
    const float* W[9];
    for (int i = 0; i < 9; i++) W[i] = (const float*)d_in[3+i];
    const float *ga[8], *ba[8];
    if (in_sizes[17] == 512){
        for (int j = 0; j < 8; j++){ ga[j] = (const float*)d_in[12+j]; ba[j] = (const float*)d_in[20+j]; }
    } else {
        for (int j = 0; j < 8; j++){ ga[j] = (const float*)d_in[12+2*j]; ba[j] = (const float*)d_in[13+2*j]; }
    }
    float* out = (float*)d_out;

    float* F; double* D;
    cudaGetSymbolAddress((void**)&F, g_f);
    cudaGetSymbolAddress((void**)&D, g_d);
    unsigned long long *near0, *near1, *near2;
    cudaGetSymbolAddress((void**)&near0, g_near0);
    cudaGetSymbolAddress((void**)&near1, g_near1);
    cudaGetSymbolAddress((void**)&near2, g_near2);
    int *cnt0, *cnt1;
    cudaGetSymbolAddress((void**)&cnt0, g_cnt0);
    cudaGetSymbolAddress((void**)&cnt1, g_cnt1);

    float *xp3 = F+F_XP3, *xgp3 = F+F_XGP3;
    float *x1 = F+F_X1, *x2 = F+F_X2, *x3 = F+F_X3;
    float *x1g = F+F_X1G, *x2g = F+F_X2G, *x3g = F+F_X3G;
    float *P = F+F_P, *R = F+F_R, *Q = F+F_Q, *gn = F+F_GNRM, *maxb = F+F_MAXB;
    float *y7 = F+F_Y7, *y8 = F+F_Y8;
    float2 *W6P = (float2*)(F+F_W6P), *W7P = (float2*)(F+F_W7P);
    float2 *W8P = (float2*)(F+F_W8P), *W9P = (float2*)(F+F_W9P);
    float *W2T = F+F_W2T, *W4T = F+F_W4T, *c7 = F+F_C7;
    float *sc0 = F+F_SC0, *bi0 = F+F_BI0, *sc1 = F+F_SC1, *bi1 = F+F_BI1;
    float *QS = F+F_QS, *QS2 = F+F_QS2, *QM = F+F_QM;

    k_setup<<<96, 256>>>(x, xg, W[1], W[3], W[5], W[6], W[7], W[8],
                         xp3, xgp3, W2T, W4T, W6P, W7P, W8P, W9P);

    int graph3_blocks = NB*MM/4 + 512;
    int graph64_blocks = NB*MM/4 + 256;
    int xg_blocks = (NB*NN*64 + NB*MM*64)/256;
    int prep_blocks = NB*NN*64/256 + NB*MM*64/256 + 4;

    // ---- stage 1 (C=3) ----
    k_stageprep<3><<<prep_blocks, 256>>>(xp3, xgp3, W[0], P, R, Q, gn);
    k_graph<3><<<graph3_blocks, 128>>>(xp3, xgp3, gn, Q, QS, QS2, QM, near0);
    k_ptstats<<<NB*NN/64, 256>>>(P, R, QS, QS2, near0, D+0, D+64, cnt0, 1);
    k_scanbn<<<2, 1024>>>(cnt0, D+0, D+64, ga[0], ba[0], sc0, bi0);
    k_scatter<<<NB*NN/256, 256>>>(near0);
    k_convb<<<4*NB*MM, 128>>>(P, R, Q, W2T, sc0, bi0, cnt0, maxb, D+128, D+192);
    k_bnparams<<<1, 512>>>(D+128, D+192, ga[1], ba[1], 64, 409600.0, sc1, bi1);
    k_xg<<<xg_blocks, 256>>>(maxb, sc1, bi1, FPS, x1, x1g);

    // ---- stage 2 (C=64) ----
    k_stageprep<64><<<prep_blocks, 256>>>(x1, x1g, W[2], P, R, Q, gn);
    k_graph<64><<<graph64_blocks, 128>>>(x1, x1g, gn, Q, QS, QS2, QM, near1);
    k_ptstats<<<NB*NN/64, 256>>>(P, R, QS, QS2, near1, D+256, D+320, cnt1, 1);
    k_scanbn<<<2, 1024>>>(cnt1, D+256, D+320, ga[2], ba[2], sc0, bi0);
    k_scatter<<<NB*NN/256, 256>>>(near1);
    k_convb<<<4*NB*MM, 128>>>(P, R, Q, W4T, sc0, bi0, cnt1, maxb, D+384, D+448);
    k_bnparams<<<1, 512>>>(D+384, D+448, ga[3], ba[3], 64, 409600.0, sc1, bi1);
    k_xg<<<xg_blocks, 256>>>(maxb, sc1, bi1, FPS, x2, x2g);

    // ---- stage 3 (C=64, W5 only) ----
    k_stageprep<64><<<prep_blocks, 256>>>(x2, x2g, W[4], P, R, Q, gn);
    k_graph<64><<<graph64_blocks, 128>>>(x2, x2g, gn, Q, QS, QS2, QM, near2);
    k_ptstats<<<NB*NN/64, 256>>>(P, R, QS, QS2, near2, D+512, D+576, cnt1, 0);
    k_bnparams<<<1, 512>>>(D+512, D+576, ga[4], ba[4], 64, 409600.0, sc0, bi0);
    k_x3g<<<xg_blocks, 256>>>(P, R, QM, near2, sc0, bi0, FPS, x3, x3g);

    // ---- tail ----
    k_y6stats<<<dim3(NB*MM/16, 4), 128>>>(x1g, x2g, x3g, W6P, D+640, D+1152);
    k_bnparams<<<1, 512>>>(D+640, D+1152, ga[5], ba[5], 512, 1024.0, sc0, bi0);
    k_c7<<<1, 256>>>(W[6], sc0, bi0, c7);
    k_y7<<<NB*NN/16, 128>>>(x1, x2, x3, W7P, c7, y7, D+1664, D+1792);
    k_bnparams<<<1, 512>>>(D+1664, D+1792, ga[6], ba[6], 128, 8192.0, sc1, bi1);
    k_y8<<<NB*NN/16, 64>>>(y7, W8P, sc1, bi1, y8, D+1920, D+1984);
    k_bnparams<<<1, 512>>>(D+1920, D+1984, ga[7], ba[7], 64, 8192.0, sc0, bi0);
    k_out<<<NB*NN/16, 128>>>(y8, W9P, sc0, bi0, out);
}

// round 12
// speedup vs baseline: 1.1329x; 1.1329x over previous
#include <cuda_runtime.h>
#include <math.h>

#define NB 2
#define NN 4096
#define MM 512
#define KK 50
#define EPSc 1e-5

typedef unsigned long long u64;

// ---------------- f32x2 packed helpers ----------------
__device__ __forceinline__ u64 pk2(float lo, float hi){
    u64 d;
    asm("mov.b64 %0, {%1, %2};" : "=l"(d)
        : "r"(__float_as_uint(lo)), "r"(__float_as_uint(hi)));
    return d;
}
__device__ __forceinline__ void upk2(float& lo, float& hi, u64 d){
    unsigned a, b;
    asm("mov.b64 {%0, %1}, %2;" : "=r"(a), "=r"(b) : "l"(d));
    lo = __uint_as_float(a); hi = __uint_as_float(b);
}
__device__ __forceinline__ u64 fma2(u64 a, u64 b, u64 c){
    u64 d;
    asm("fma.rn.f32x2 %0, %1, %2, %3;" : "=l"(d) : "l"(a), "l"(b), "l"(c));
    return d;
}
__device__ __forceinline__ u64 add2(u64 a, u64 b){
    u64 d;
    asm("add.rn.f32x2 %0, %1, %2;" : "=l"(d) : "l"(a), "l"(b));
    return d;
}
__device__ __forceinline__ u64 sub2(u64 a, u64 b){
    u64 d;
    asm("sub.rn.f32x2 %0, %1, %2;" : "=l"(d) : "l"(a), "l"(b));
    return d;
}
__device__ __forceinline__ float hsum2(u64 a){
    float lo, hi; upk2(lo, hi, a); return lo + hi;
}
__device__ __forceinline__ u64 shflmin64(u64 v, int off){
    unsigned lo = (unsigned)v, hi = (unsigned)(v >> 32);
    unsigned olo = __shfl_down_sync(0xffffffffu, lo, off);
    unsigned ohi = __shfl_down_sync(0xffffffffu, hi, off);
    u64 o = ((u64)ohi << 32) | olo;
    return o < v ? o : v;
}

// ---------------- scratch layout (floats) ----------------
#define F_XP3   0
#define F_XGP3  (F_XP3+NB*NN*3)
#define F_X1    (F_XGP3+NB*MM*3)
#define F_X2    (F_X1+NB*NN*64)
#define F_X3    (F_X2+NB*NN*64)
#define F_X1G   (F_X3+NB*NN*64)
#define F_X2G   (F_X1G+NB*MM*64)
#define F_X3G   (F_X2G+NB*MM*64)
#define F_P     (F_X3G+NB*MM*64)
#define F_R     (F_P+NB*NN*64)
#define F_Q     (F_R+NB*NN*64)
#define F_GNRM  (F_Q+NB*MM*64)
#define F_MAXB  (F_GNRM+NB*MM)
#define F_Y7    (F_MAXB+NB*NN*64)
#define F_Y8    (F_Y7+NB*NN*128)
#define F_W6P   (F_Y8+NB*NN*64)
#define F_W7P   (F_W6P+96*512*2)
#define F_W8P   (F_W7P+96*128*2)
#define F_W9P   (F_W8P+64*64*2)
#define F_W2T   (F_W9P+32*128*2)
#define F_W4T   (F_W2T+64*64)
#define F_C7    (F_W4T+64*64)
#define F_SC0   (F_C7+NB*128)
#define F_BI0   (F_SC0+512)
#define F_SC1   (F_BI0+512)
#define F_BI1   (F_SC1+512)
#define F_QS    (F_BI1+512)
#define F_QS2   (F_QS+NB*MM*64)
#define F_QM    (F_QS2+NB*MM*64)
#define F_TOT   (F_QM+NB*MM*64)

__device__ float g_f[F_TOT];
__device__ double g_d[2048];
__device__ unsigned long long g_near0[NB*NN];
__device__ unsigned long long g_near1[NB*NN];
__device__ unsigned long long g_near2[NB*NN];
__device__ int g_nbr[NB*MM*KK];
__device__ int g_cnt0[NB*MM];
__device__ int g_cnt1[NB*MM];
__device__ int g_offs[NB*MM];
__device__ int g_woffs[NB*MM];
__device__ int g_order[NB*NN];
__device__ unsigned g_max6[NB*512];

__device__ __forceinline__ unsigned long long packkey(float d, int m){
    unsigned u = __float_as_uint(d);
    u = (u & 0x80000000u) ? ~u : (u | 0x80000000u);
    return (((unsigned long long)u) << 32) | (unsigned)m;
}
__device__ __forceinline__ unsigned f2ord(float x){
    unsigned u = __float_as_uint(x);
    return (u & 0x80000000u) ? ~u : (u | 0x80000000u);
}
__device__ __forceinline__ float ord2f(unsigned u){
    return (u & 0x80000000u) ? __uint_as_float(u ^ 0x80000000u) : __uint_as_float(~u);
}
__device__ __forceinline__ float lrelu_f(float v){ return v >= 0.f ? v : 0.2f*v; }

// ---------------- setup: init + transpose + weight packing ----------------
__global__ void k_setup(const float* __restrict__ x, const float* __restrict__ xg,
                        const float* __restrict__ W2, const float* __restrict__ W4,
                        const float* __restrict__ W6, const float* __restrict__ W7,
                        const float* __restrict__ W8, const float* __restrict__ W9,
                        float* __restrict__ xp, float* __restrict__ xgp,
                        float* __restrict__ W2T, float* __restrict__ W4T,
                        float2* __restrict__ W6P, float2* __restrict__ W7P,
                        float2* __restrict__ W8P, float2* __restrict__ W9P){
    int stride = gridDim.x*blockDim.x;
    int i0 = blockIdx.x*blockDim.x + threadIdx.x;
    for (int i = i0; i < 2048; i += stride) g_d[i] = 0.0;
    for (int i = i0; i < NB*NN; i += stride){
        g_near0[i] = ~0ULL; g_near1[i] = ~0ULL; g_near2[i] = ~0ULL;
    }
    for (int i = i0; i < NB*MM; i += stride){ g_cnt0[i] = 0; g_cnt1[i] = 0; }
    for (int i = i0; i < NB*512; i += stride) g_max6[i] = 0u;
    for (int i = i0; i < NB*NN*3; i += stride){
        int b = i/(NN*3); int rem = i - b*NN*3; int n = rem/3; int c = rem - n*3;
        xp[i] = x[(b*3 + c)*NN + n];
    }
    for (int i = i0; i < NB*MM*3; i += stride){
        int b = i/(MM*3); int rem = i - b*MM*3; int m = rem/3; int c = rem - m*3;
        xgp[i] = xg[(b*3 + c)*MM + m];
    }
    for (int i = i0; i < 96*512; i += stride){
        int c2 = i/512, o = i - c2*512;
        W6P[i] = make_float2(W6[o*192 + 2*c2], W6[o*192 + 2*c2 + 1]);
    }
    for (int i = i0; i < 96*128; i += stride){
        int c2 = i/128, o = i - c2*128;
        W7P[i] = make_float2(W7[o*704 + 512 + 2*c2], W7[o*704 + 512 + 2*c2 + 1]);
    }
    for (int i = i0; i < 64*64; i += stride){
        int c2 = i >> 6, o = i & 63;
        W8P[i] = make_float2(W8[o*128 + 2*c2], W8[o*128 + 2*c2 + 1]);
    }
    for (int i = i0; i < 32*128; i += stride){
        int c2 = i >> 7, o = i & 127;
        W9P[i] = make_float2(W9[o*64 + 2*c2], W9[o*64 + 2*c2 + 1]);
    }
    for (int i = i0; i < 64*64; i += stride){
        int o = i >> 6, c = i & 63;
        W2T[c*64 + o] = W2[i];
        W4T[c*64 + o] = W4[i];
    }
}

// ---------------- fused stage prep: pqr + q + gn ----------------
template<int C>
__global__ void k_stageprep(const float* __restrict__ X, const float* __restrict__ G,
                            const float* __restrict__ W,
                            float* __restrict__ P, float* __restrict__ R,
                            float* __restrict__ Q, float* __restrict__ gn){
    const int BA = NB*NN*64/256;
    const int BB = NB*MM*64/256;
    int bid = blockIdx.x;
    if (bid < BA){
        int i = bid*256 + threadIdx.x;
        int o = i & 63; int pn = i >> 6;
        if (C == 3){
            const float* Xp = X + (size_t)pn*3;
            const float* Wo = W + (size_t)o*6;
            float p = 0.f, r = 0.f;
            #pragma unroll
            for (int c = 0; c < 3; c++){
                float xv = Xp[c]; float wl = Wo[c]; float wh = Wo[3 + c];
                p = fmaf(wh - wl, xv, p);
                r = fmaf(wl, xv, r);
            }
            P[i] = p; R[i] = r;
        } else {
            const u64* X2 = (const u64*)(X + (size_t)pn*64);
            const u64* WL = (const u64*)(W + (size_t)o*128);
            u64 pa = 0, pb = 0, ra = 0, rb = 0;
            #pragma unroll
            for (int c2 = 0; c2 < 32; c2 += 2){
                u64 xv0 = X2[c2], xv1 = X2[c2+1];
                u64 wl0 = WL[c2], wl1 = WL[c2+1];
                u64 wh0 = WL[32+c2], wh1 = WL[32+c2+1];
                pa = fma2(sub2(wh0, wl0), xv0, pa);
                ra = fma2(wl0, xv0, ra);
                pb = fma2(sub2(wh1, wl1), xv1, pb);
                rb = fma2(wl1, xv1, rb);
            }
            P[i] = hsum2(add2(pa, pb));
            R[i] = hsum2(add2(ra, rb));
        }
    } else if (bid < BA + BB){
        int i = (bid - BA)*256 + threadIdx.x;
        int o = i & 63; int pm = i >> 6;
        if (C == 3){
            const float* Gp = G + (size_t)pm*3;
            const float* Wo = W + (size_t)o*6;
            float q = 0.f;
            #pragma unroll
            for (int c = 0; c < 3; c++) q = fmaf(Wo[c], Gp[c], q);
            Q[i] = q;
        } else {
            const u64* G2 = (const u64*)(G + (size_t)pm*64);
            const u64* WL = (const u64*)(W + (size_t)o*128);
            u64 qa = 0, qb = 0;
            #pragma unroll
            for (int c2 = 0; c2 < 32; c2 += 2){
                qa = fma2(WL[c2], G2[c2], qa);
                qb = fma2(WL[c2+1], G2[c2+1], qb);
            }
            Q[i] = hsum2(add2(qa, qb));
        }
    } else {
        int i = (bid - BA - BB)*256 + threadIdx.x;
        if (i >= NB*MM) return;
        if (C == 3){
            const float* Gp = G + (size_t)i*3;
            gn[i] = Gp[0]*Gp[0] + Gp[1]*Gp[1] + Gp[2]*Gp[2];
        } else {
            const u64* G2 = (const u64*)(G + (size_t)i*64);
            u64 a = 0, b = 0;
            #pragma unroll
            for (int c2 = 0; c2 < 32; c2 += 2){
                a = fma2(G2[c2], G2[c2], a);
                b = fma2(G2[c2+1], G2[c2+1], b);
            }
            gn[i] = hsum2(add2(a, b));
        }
    }
}

// ---------------- fused graph: 50-NN (register top-k, exact keys) + per-cell qsum + nearest ----------------
template<int C>
__global__ void __launch_bounds__(128)
k_graph(const float* __restrict__ X, const float* __restrict__ G,
        const float* __restrict__ gn, const float* __restrict__ Q,
        float* __restrict__ QS, float* __restrict__ QS2, float* __restrict__ QM,
        unsigned long long* __restrict__ nearp){
    const int NBRB = NB*MM/4;
    __shared__ int snbr_s[4][KK];
    if (blockIdx.x < NBRB){
        int w = threadIdx.x >> 5, lane = threadIdx.x & 31;
        int cell = blockIdx.x*4 + w;
        int b = cell >> 9, m = cell & 511;
        const float* Gb = G + (size_t)b*MM*C;
        float cm[C];
        #pragma unroll
        for (int c = 0; c < C; c++) cm[c] = Gb[(size_t)m*C + c];
        float gm = gn[b*MM + m];
        u64 key[16];
        #pragma unroll
        for (int t = 0; t < 16; t++){
            int j = t*32 + lane;
            float dot = 0.f;
            if (C == 64){
                const float4* Gr = (const float4*)(Gb + (size_t)j*64);
                #pragma unroll
                for (int c4 = 0; c4 < 16; c4++){
                    float4 g = Gr[c4];
                    dot = fmaf(cm[4*c4],   g.x, dot);
                    dot = fmaf(cm[4*c4+1], g.y, dot);
                    dot = fmaf(cm[4*c4+2], g.z, dot);
                    dot = fmaf(cm[4*c4+3], g.w, dot);
                }
            } else {
                #pragma unroll
                for (int c = 0; c < C; c++) dot = fmaf(cm[c], Gb[(size_t)j*C + c], dot);
            }
            float d = gm + gn[b*MM + j] - 2.f*dot;
            key[t] = (j == m) ? (u64)j : ((((u64)f2ord(d)) << 32) | (unsigned)j);
        }
        int* nout = g_nbr + (size_t)cell*KK;
        for (int k = 0; k < KK; k++){
            u64 bk = key[0];
            #pragma unroll
            for (int t = 1; t < 16; t++) bk = min(bk, key[t]);
            bk = shflmin64(bk, 16);
            bk = shflmin64(bk, 8);
            bk = shflmin64(bk, 4);
            bk = shflmin64(bk, 2);
            bk = shflmin64(bk, 1);
            unsigned lo = __shfl_sync(0xffffffffu, (unsigned)bk, 0);
            int bj = (int)(lo & 511u);
            if (lane == 0){ nout[k] = bj; snbr_s[w][k] = bj; }
            if ((bj & 31) == lane) key[bj >> 5] = ~0ULL;
        }
        __syncwarp();
        u64 qs = 0, q2 = 0;
        float qmlo = -INFINITY, qmhi = -INFINITY;
        #pragma unroll 7
        for (int k = 1; k < KK; k++){
            int mk = snbr_s[w][k];
            u64 q = *(const u64*)(Q + ((size_t)(b*MM + mk))*64 + 2*lane);
            qs = add2(qs, q);
            q2 = fma2(q, q, q2);
            float lo2, hi2; upk2(lo2, hi2, q);
            qmlo = fmaxf(qmlo, lo2); qmhi = fmaxf(qmhi, hi2);
        }
        *(u64*)(QS  + (size_t)cell*64 + 2*lane) = qs;
        *(u64*)(QS2 + (size_t)cell*64 + 2*lane) = q2;
        *(u64*)(QM  + (size_t)cell*64 + 2*lane) = pk2(qmlo, qmhi);
    } else {
        int t = blockIdx.x - NBRB;
        if (C == 3){
            int bx = t & 31, by = (t >> 5) & 7, bz = t >> 8;
            int m0 = by*64;
            int n = bx*128 + threadIdx.x;
            __shared__ float sg[64*3];
            __shared__ float sgn[64];
            const float* Gb = G + ((size_t)bz*MM + m0)*3;
            for (int i = threadIdx.x; i < 64*3; i += 128) sg[i] = Gb[i];
            if (threadIdx.x < 64) sgn[threadIdx.x] = gn[bz*MM + m0 + threadIdx.x];
            __syncthreads();
            const float* Xp = X + ((size_t)bz*NN + n)*3;
            float x0 = Xp[0], x1 = Xp[1], x2 = Xp[2];
            float best = INFINITY; int bi = 0;
            for (int j = 0; j < 64; j++){
                float dot = x0*sg[j*3] + x1*sg[j*3+1] + x2*sg[j*3+2];
                float d = sgn[j] - 2.f*dot;
                if (d < best){ best = d; bi = m0 + j; }
            }
            atomicMin(&nearp[(size_t)bz*NN + n], packkey(best, bi));
        } else {
            int bx = t & 15, by = (t >> 4) & 7, bz = t >> 7;
            int m0 = by*64;
            int tid = threadIdx.x;
            int n0 = bx*256 + tid;
            __shared__ __align__(16) float sg[64*64];
            __shared__ float sgn[64];
            const float4* Gb4 = (const float4*)(G + ((size_t)bz*MM + m0)*64);
            for (int i = tid; i < 64*16; i += 128) ((float4*)sg)[i] = Gb4[i];
            if (tid < 64) sgn[tid] = gn[bz*MM + m0 + tid];
            __syncthreads();
            u64 xp0[32], xp1[32];
            const u64* X0 = (const u64*)(X + ((size_t)bz*NN + n0)*64);
            const u64* X1 = (const u64*)(X + ((size_t)bz*NN + n0 + 128)*64);
            #pragma unroll
            for (int c2 = 0; c2 < 32; c2++){ xp0[c2] = X0[c2]; xp1[c2] = X1[c2]; }
            float best0 = INFINITY, best1 = INFINITY; int bi0 = 0, bi1 = 0;
            for (int j = 0; j < 64; j++){
                const ulonglong2* g2 = (const ulonglong2*)(sg + j*64);
                u64 a0 = 0, a1 = 0, b0 = 0, b1 = 0;
                #pragma unroll
                for (int i = 0; i < 16; i++){
                    ulonglong2 tt = g2[i];
                    a0 = fma2(xp0[2*i],   tt.x, a0);
                    a1 = fma2(xp0[2*i+1], tt.y, a1);
                    b0 = fma2(xp1[2*i],   tt.x, b0);
                    b1 = fma2(xp1[2*i+1], tt.y, b1);
                }
                float gnj = sgn[j];
                float d0 = gnj - 2.f*hsum2(add2(a0, a1));
                float d1 = gnj - 2.f*hsum2(add2(b0, b1));
                if (d0 < best0){ best0 = d0; bi0 = m0 + j; }
                if (d1 < best1){ best1 = d1; bi1 = m0 + j; }
            }
            atomicMin(&nearp[(size_t)bz*NN + n0],       packkey(best0, bi0));
            atomicMin(&nearp[(size_t)bz*NN + n0 + 128], packkey(best1, bi1));
        }
    }
}

// ---------------- analytic BN stats of y_a over (n,k): fp32 accum, double reduce ----------------
__global__ void k_ptstats(const float* __restrict__ P, const float* __restrict__ R,
                          const float* __restrict__ QS, const float* __restrict__ QS2,
                          const unsigned long long* __restrict__ nearp,
                          double* __restrict__ gsum, double* __restrict__ gsq,
                          int* __restrict__ cnt, int withhist){
    int tid = threadIdx.x; int slot = tid >> 6; int o = tid & 63;
    float s = 0.f, q = 0.f;
    #pragma unroll
    for (int i = 0; i < 8; i++){
        int pn = blockIdx.x*32 + i*4 + slot;
        int b = pn >> 12;
        int nr = (int)(nearp[pn] & 0xFFFFFFFFu);
        float p  = P[(size_t)pn*64 + o];
        float r  = R[(size_t)pn*64 + o];
        float qs = QS[((size_t)(b*MM + nr))*64 + o];
        float q2 = QS2[((size_t)(b*MM + nr))*64 + o];
        float rq = r + qs;
        s += fmaf(50.f, p, rq);
        q += fmaf(50.f*p, p, fmaf(2.f*p, rq, fmaf(r, r, q2)));
        if (withhist && o == 0) atomicAdd(&cnt[b*MM + nr], 1);
    }
    __shared__ float sS[256], sQ[256];
    sS[tid] = s; sQ[tid] = q;
    __syncthreads();
    if (tid < 64){
        double ds = (double)sS[tid] + (double)sS[tid+64] + (double)sS[tid+128] + (double)sS[tid+192];
        double dq = (double)sQ[tid] + (double)sQ[tid+64] + (double)sQ[tid+128] + (double)sQ[tid+192];
        atomicAdd(&gsum[tid], ds);
        atomicAdd(&gsq[tid], dq);
    }
}

// ---------------- scan + bnparams fused ----------------
__global__ void k_scanbn(const int* __restrict__ cnt,
                         const double* __restrict__ sum, const double* __restrict__ sq,
                         const float* __restrict__ gma, const float* __restrict__ bta,
                         float* __restrict__ sc, float* __restrict__ bi){
    if (blockIdx.x == 0){
        __shared__ int s[NB*MM];
        int tid = threadIdx.x;
        s[tid] = cnt[tid];
        __syncthreads();
        for (int off = 1; off < NB*MM; off <<= 1){
            int v = (tid >= off) ? s[tid-off] : 0;
            __syncthreads();
            s[tid] += v;
            __syncthreads();
        }
        int e = s[tid] - cnt[tid];
        g_offs[tid] = e; g_woffs[tid] = e;
    } else {
        int o = threadIdx.x;
        if (o >= 64) return;
        double mean = sum[o]/409600.0;
        double var = sq[o]/409600.0 - mean*mean;
        if (var < 0.0) var = 0.0;
        double s = (double)gma[o] / sqrt(var + (double)EPSc);
        sc[o] = (float)s;
        bi[o] = (float)((double)bta[o] - mean*s);
    }
}

__global__ void k_scatter(const unsigned long long* __restrict__ nearp){
    int pn = blockIdx.x*blockDim.x + threadIdx.x;
    if (pn >= NB*NN) return;
    int nr = (int)(nearp[pn] & 0xFFFFFFFFu);
    int pos = atomicAdd(&g_woffs[(pn >> 12)*MM + nr], 1);
    g_order[pos] = pn;
}

// ---------------- BN params (standalone) ----------------
__global__ void k_bnparams(const double* __restrict__ sum, const double* __restrict__ sq,
                           const float* __restrict__ gma, const float* __restrict__ bta,
                           int nch, double cnt, float* __restrict__ sc, float* __restrict__ bi){
    int o = threadIdx.x;
    if (o >= nch) return;
    double mean = sum[o]/cnt;
    double var = sq[o]/cnt - mean*mean;
    if (var < 0.0) var = 0.0;
    double s = (double)gma[o] / sqrt(var + (double)EPSc);
    sc[o] = (float)s;
    bi[o] = (float)((double)bta[o] - mean*s);
}

// ---------------- fused second edge-conv: 2 blocks per cell, k-chunks of 25 ----------------
__global__ void __launch_bounds__(128)
k_convb(const float* __restrict__ P, const float* __restrict__ R, const float* __restrict__ Q,
        const float* __restrict__ WT, const float* __restrict__ scA, const float* __restrict__ biA,
        const int* __restrict__ cnt, float* __restrict__ gmax,
        double* __restrict__ gsum, double* __restrict__ gsq){
    __shared__ float Qs[KK*64];
    __shared__ __align__(16) float2 hs[2][25][64];
    __shared__ int snbr[KK];
    int cell = blockIdx.x >> 1;
    int halfsel = blockIdx.x & 1;
    int count0 = cnt[cell];
    if (count0 == 0) return;
    int h1 = (count0 + 1) >> 1;
    int count = halfsel ? (count0 - h1) : h1;
    if (count <= 0) return;
    int start = g_offs[cell] + (halfsel ? h1 : 0);
    int b = cell >> 9;
    int tid = threadIdx.x, half = tid >> 6, o = tid & 63;
    if (tid < KK) snbr[tid] = g_nbr[(size_t)cell*KK + tid];
    if (tid < 64) Qs[tid] = 0.f;
    __syncthreads();
    for (int idx = tid; idx < 49*64; idx += 128){
        int k = 1 + (idx >> 6), oo = idx & 63;
        Qs[k*64 + oo] = Q[((size_t)(b*MM + snbr[k]))*64 + oo];
    }
    u64 Wd[64];
    #pragma unroll
    for (int c = 0; c < 64; c++){ float w = WT[c*64 + o]; Wd[c] = pk2(w, w); }
    float sc = scA[o], bi = biA[o];
    __syncthreads();
    int barid = half + 1;
    double dsum = 0.0, dsq = 0.0;
    for (int pi = 0; pi < count; pi += 4){
        int iA = pi + 2*half, iB = iA + 1;
        bool vA = iA < count, vB = iB < count;
        int pA = g_order[start + (vA ? iA : 0)];
        int pB = g_order[start + (vB ? iB : 0)];
        float p0 = P[(size_t)pA*64 + o], r0 = R[(size_t)pA*64 + o];
        float p1 = P[(size_t)pB*64 + o], r1 = R[(size_t)pB*64 + o];
        float fsA = 0.f, fqA = 0.f, mxA = -INFINITY;
        float fsB = 0.f, fqB = 0.f, mxB = -INFINITY;
        for (int cc = 0; cc < 2; cc++){
            #pragma unroll
            for (int j = 0; j < 25; j++){
                int k = cc*25 + j;
                float q = Qs[k*64 + o];
                float v0 = (k == 0) ? (p0 + r0) : (p0 + q);
                float v1 = (k == 0) ? (p1 + r1) : (p1 + q);
                float h0 = lrelu_f(fmaf(v0, sc, bi));
                float h1 = lrelu_f(fmaf(v1, sc, bi));
                hs[half][j][o] = make_float2(h0, h1);
            }
            asm volatile("bar.sync %0, 64;" :: "r"(barid) : "memory");
            #pragma unroll 5
            for (int j = 0; j < 25; j++){
                const ulonglong2* h4 = (const ulonglong2*)hs[half][j];
                u64 a0 = 0, a1 = 0, a2 = 0, a3 = 0;
                #pragma unroll
                for (int c2 = 0; c2 < 32; c2 += 2){
                    ulonglong2 t0 = h4[c2];
                    ulonglong2 t1 = h4[c2+1];
                    a0 = fma2(Wd[2*c2],   t0.x, a0);
                    a1 = fma2(Wd[2*c2+1], t0.y, a1);
                    a2 = fma2(Wd[2*c2+2], t1.x, a2);
                    a3 = fma2(Wd[2*c2+3], t1.y, a3);
                }
                u64 s2 = add2(add2(a0, a1), add2(a2, a3));
                float yA, yB; upk2(yA, yB, s2);
                if (vA){ fsA += yA; fqA = fmaf(yA, yA, fqA); mxA = fmaxf(mxA, yA); }
                if (vB){ fsB += yB; fqB = fmaf(yB, yB, fqB); mxB = fmaxf(mxB, yB); }
            }
            asm volatile("bar.sync %0, 64;" :: "r"(barid) : "memory");
        }
        if (vA){ gmax[(size_t)pA*64 + o] = mxA; dsum += fsA; dsq += fqA; }
        if (vB){ gmax[(size_t)pB*64 + o] = mxB; dsum += fsB; dsq += fqB; }
    }
    atomicAdd(&gsum[o], dsum);
    atomicAdd(&gsq[o], dsq);
}

// ---------------- x = lrelu(bn(maxb)) + gather (fused) ----------------
__global__ void k_xg(const float* __restrict__ gmax, const float* __restrict__ sc,
                     const float* __restrict__ bi, const int* __restrict__ FPS,
                     float* __restrict__ X, float* __restrict__ XG){
    int i = blockIdx.x*blockDim.x + threadIdx.x;
    if (i < NB*NN*64){
        int o = i & 63;
        X[i] = lrelu_f(fmaf(gmax[i], sc[o], bi[o]));
    } else {
        int j = i - NB*NN*64;
        if (j >= NB*MM*64) return;
        int o = j & 63; int pm = j >> 6; int b = pm >> 9; int m = pm & 511;
        int n = FPS[b*MM + m];
        XG[j] = lrelu_f(fmaf(gmax[(((size_t)b*NN) + n)*64 + o], sc[o], bi[o]));
    }
}

// ---------------- stage3: x3 = lrelu(bn(P + max(R, QM[near]))) + gather ----------------
__global__ void k_x3g(const float* __restrict__ P, const float* __restrict__ R,
                      const float* __restrict__ QM,
                      const unsigned long long* __restrict__ nearp,
                      const float* __restrict__ sc, const float* __restrict__ bi,
                      const int* __restrict__ FPS,
                      float* __restrict__ X, float* __restrict__ XG){
    int i = blockIdx.x*blockDim.x + threadIdx.x;
    if (i < NB*NN*64){
        int o = i & 63; int pn = i >> 6; int b = pn >> 12;
        int nr = (int)(nearp[pn] & 0xFFFFFFFFu);
        float v = P[i] + fmaxf(R[i], QM[((size_t)(b*MM + nr))*64 + o]);
        X[i] = lrelu_f(fmaf(v, sc[o], bi[o]));
    } else {
        int j = i - NB*NN*64;
        if (j >= NB*MM*64) return;
        int o = j & 63; int pm = j >> 6; int b = pm >> 9; int m = pm & 511;
        int pn = b*NN + FPS[b*MM + m];
        int nr = (int)(nearp[pn] & 0xFFFFFFFFu);
        float v = P[(size_t)pn*64 + o] + fmaxf(R[(size_t)pn*64 + o], QM[((size_t)(b*MM + nr))*64 + o]);
        XG[j] = lrelu_f(fmaf(v, sc[o], bi[o]));
    }
}

// ---------------- y6 = W6 * [x1g;x2g;x3g], stats + per-(b,o) max (packed) ----------------
__global__ void k_y6stats(const float* __restrict__ x1g, const float* __restrict__ x2g,
                          const float* __restrict__ x3g, const float2* __restrict__ WP,
                          double* __restrict__ gsum, double* __restrict__ gsq){
    __shared__ __align__(16) float sF[16][192];
    int tid = threadIdx.x; int pm0 = blockIdx.x*16; int b = pm0 >> 9;
    for (int idx = tid; idx < 16*192; idx += 128){
        int p = idx/192, c = idx - p*192; int pm = pm0 + p;
        float v = (c < 64) ? x1g[(size_t)pm*64 + c]
                : (c < 128) ? x2g[(size_t)pm*64 + c - 64]
                            : x3g[(size_t)pm*64 + c - 128];
        sF[p][c] = v;
    }
    __syncthreads();
    int o = blockIdx.y*128 + tid;
    const u64* W2p = (const u64*)WP;
    double s = 0.0, q = 0.0; float mx = -INFINITY;
    for (int p0 = 0; p0 < 16; p0 += 4){
        const u64* f0 = (const u64*)sF[p0+0];
        const u64* f1 = (const u64*)sF[p0+1];
        const u64* f2 = (const u64*)sF[p0+2];
        const u64* f3 = (const u64*)sF[p0+3];
        u64 a0 = 0, a1 = 0, a2 = 0, a3 = 0;
        for (int c2 = 0; c2 < 96; c2++){
            u64 wp = W2p[c2*512 + o];
            a0 = fma2(wp, f0[c2], a0);
            a1 = fma2(wp, f1[c2], a1);
            a2 = fma2(wp, f2[c2], a2);
            a3 = fma2(wp, f3[c2], a3);
        }
        float y0 = hsum2(a0), y1 = hsum2(a1), y2 = hsum2(a2), y3 = hsum2(a3);
        s += (double)y0 + (double)y1 + (double)y2 + (double)y3;
        q += (double)y0*y0 + (double)y1*y1 + (double)y2*y2 + (double)y3*y3;
        mx = fmaxf(fmaxf(fmaxf(mx, y0), fmaxf(y1, y2)), y3);
    }
    atomicAdd(&gsum[o], s);
    atomicAdd(&gsq[o], q);
    atomicMax(&g_max6[b*512 + o], f2ord(mx));
}

// ---------------- c7[b,o] = W7[:, :512] . lrelu(bn6(y6max)) ----------------
__global__ void k_c7(const float* __restrict__ W7, const float* __restrict__ sc,
                     const float* __restrict__ bi, float* __restrict__ c7){
    int t = threadIdx.x; int b = t >> 7, o = t & 127;
    float acc = 0.f;
    for (int c = 0; c < 512; c++){
        float v = ord2f(g_max6[b*512 + c]);
        float h = fmaf(v, sc[c], bi[c]);
        h = (h >= 0.f) ? h : 0.2f*h;
        acc = fmaf(W7[(size_t)o*704 + c], h, acc);
    }
    c7[t] = acc;
}

// ---------------- y7 = c7 + W7[:,512:] * [x1;x2;x3], stats (packed) ----------------
__global__ void k_y7(const float* __restrict__ x1, const float* __restrict__ x2,
                     const float* __restrict__ x3, const float2* __restrict__ WP,
                     const float* __restrict__ c7, float* __restrict__ y7,
                     double* __restrict__ gsum, double* __restrict__ gsq){
    __shared__ __align__(16) float sF[16][192];
    int tid = threadIdx.x; int pn0 = blockIdx.x*16; int b = pn0 >> 12;
    for (int idx = tid; idx < 16*192; idx += 128){
        int p = idx/192, c = idx - p*192; int pn = pn0 + p;
        float v = (c < 64) ? x1[(size_t)pn*64 + c]
                : (c < 128) ? x2[(size_t)pn*64 + c - 64]
                            : x3[(size_t)pn*64 + c - 128];
        sF[p][c] = v;
    }
    __syncthreads();
    int o = tid;
    float ci = c7[b*128 + o];
    const u64* W2p = (const u64*)WP;
    double s = 0.0, q = 0.0;
    for (int p0 = 0; p0 < 16; p0 += 4){
        const u64* f0 = (const u64*)sF[p0+0];
        const u64* f1 = (const u64*)sF[p0+1];
        const u64* f2 = (const u64*)sF[p0+2];
        const u64* f3 = (const u64*)sF[p0+3];
        u64 a0 = 0, a1 = 0, a2 = 0, a3 = 0;
        for (int c2 = 0; c2 < 96; c2++){
            u64 wp = W2p[c2*128 + o];
            a0 = fma2(wp, f0[c2], a0);
            a1 = fma2(wp, f1[c2], a1);
            a2 = fma2(wp, f2[c2], a2);
            a3 = fma2(wp, f3[c2], a3);
        }
        float y0 = ci + hsum2(a0), y1 = ci + hsum2(a1);
        float y2 = ci + hsum2(a2), y3 = ci + hsum2(a3);
        y7[(size_t)(pn0+p0+0)*128 + o] = y0;
        y7[(size_t)(pn0+p0+1)*128 + o] = y1;
        y7[(size_t)(pn0+p0+2)*128 + o] = y2;
        y7[(size_t)(pn0+p0+3)*128 + o] = y3;
        s += (double)y0 + (double)y1 + (double)y2 + (double)y3;
        q += (double)y0*y0 + (double)y1*y1 + (double)y2*y2 + (double)y3*y3;
    }
    atomicAdd(&gsum[o], s);
    atomicAdd(&gsq[o], q);
}

// ---------------- y8 = W8 * lrelu(bn7(y7)), stats (packed) ----------------
__global__ void k_y8(const float* __restrict__ y7, const float2* __restrict__ WP,
                     const float* __restrict__ sc7, const float* __restrict__ bi7,
                     float* __restrict__ y8, double* __restrict__ gsum, double* __restrict__ gsq){
    __shared__ __align__(16) float sF[16][128];
    int tid = threadIdx.x; int pn0 = blockIdx.x*16;
    for (int idx = tid; idx < 16*128; idx += 64){
        int p = idx >> 7, c = idx & 127;
        float v = y7[(size_t)(pn0+p)*128 + c];
        float h = fmaf(v, sc7[c], bi7[c]);
        sF[p][c] = (h >= 0.f) ? h : 0.2f*h;
    }
    __syncthreads();
    int o = tid;
    const u64* W2p = (const u64*)WP;
    double s = 0.0, q = 0.0;
    for (int p0 = 0; p0 < 16; p0 += 4){
        const u64* f0 = (const u64*)sF[p0+0];
        const u64* f1 = (const u64*)sF[p0+1];
        const u64* f2 = (const u64*)sF[p0+2];
        const u64* f3 = (const u64*)sF[p0+3];
        u64 a0 = 0, a1 = 0, a2 = 0, a3 = 0;
        for (int c2 = 0; c2 < 64; c2++){
            u64 wp = W2p[c2*64 + o];
            a0 = fma2(wp, f0[c2], a0);
            a1 = fma2(wp, f1[c2], a1);
            a2 = fma2(wp, f2[c2], a2);
            a3 = fma2(wp, f3[c2], a3);
        }
        float y0 = hsum2(a0), y1 = hsum2(a1), y2 = hsum2(a2), y3 = hsum2(a3);
        y8[(size_t)(pn0+p0+0)*64 + o] = y0;
        y8[(size_t)(pn0+p0+1)*64 + o] = y1;
        y8[(size_t)(pn0+p0+2)*64 + o] = y2;
        y8[(size_t)(pn0+p0+3)*64 + o] = y3;
        s += (double)y0 + (double)y1 + (double)y2 + (double)y3;
        q += (double)y0*y0 + (double)y1*y1 + (double)y2*y2 + (double)y3*y3;
    }
    atomicAdd(&gsum[o], s);
    atomicAdd(&gsq[o], q);
}

// ---------------- out = W9 * lrelu(bn8(y8)) (packed) ----------------
__global__ void k_out(const float* __restrict__ y8, const float2* __restrict__ WP,
                      const float* __restrict__ sc8, const float* __restrict__ bi8,
                      float* __restrict__ out){
    __shared__ __align__(16) float sF[16][64];
    int tid = threadIdx.x; int pn0 = blockIdx.x*16;
    for (int idx = tid; idx < 16*64; idx += 128){
        int p = idx >> 6, c = idx & 63;
        float v = y8[(size_t)(pn0+p)*64 + c];
        float h = fmaf(v, sc8[c], bi8[c]);
        sF[p][c] = (h >= 0.f) ? h : 0.2f*h;
    }
    __syncthreads();
    int o = tid;
    const u64* W2p = (const u64*)WP;
    for (int p0 = 0; p0 < 16; p0 += 4){
        const u64* f0 = (const u64*)sF[p0+0];
        const u64* f1 = (const u64*)sF[p0+1];
        const u64* f2 = (const u64*)sF[p0+2];
        const u64* f3 = (const u64*)sF[p0+3];
        u64 a0 = 0, a1 = 0, a2 = 0, a3 = 0;
        for (int c2 = 0; c2 < 32; c2++){
            u64 wp = W2p[c2*128 + o];
            a0 = fma2(wp, f0[c2], a0);
            a1 = fma2(wp, f1[c2], a1);
            a2 = fma2(wp, f2[c2], a2);
            a3 = fma2(wp, f3[c2], a3);
        }
        out[(size_t)(pn0+p0+0)*128 + o] = hsum2(a0);
        out[(size_t)(pn0+p0+1)*128 + o] = hsum2(a1);
        out[(size_t)(pn0+p0+2)*128 + o] = hsum2(a2);
        out[(size_t)(pn0+p0+3)*128 + o] = hsum2(a3);
    }
}

// ---------------- host ----------------
extern "C" void kernel_launch(void* const* d_in, const int* in_sizes, int n_in,
                              void* d_out, int out_size){
    const float* x  = (const float*)d_in[0];
    const float* xg = (const float*)d_in[1];
    const int* FPS  = (const int*)d_in[2];
    const float* W[9];
    for (int i = 0; i < 9; i++) W[i] = (const float*)d_in[3+i];
    const float *ga[8], *ba[8];
    if (in_sizes[17] == 512){
        for (int j = 0; j < 8; j++){ ga[j] = (const float*)d_in[12+j]; ba[j] = (const float*)d_in[20+j]; }
    } else {
        for (int j = 0; j < 8; j++){ ga[j] = (const float*)d_in[12+2*j]; ba[j] = (const float*)d_in[13+2*j]; }
    }
    float* out = (float*)d_out;

    float* F; double* D;
    cudaGetSymbolAddress((void**)&F, g_f);
    cudaGetSymbolAddress((void**)&D, g_d);
    unsigned long long *near0, *near1, *near2;
    cudaGetSymbolAddress((void**)&near0, g_near0);
    cudaGetSymbolAddress((void**)&near1, g_near1);
    cudaGetSymbolAddress((void**)&near2, g_near2);
    int *cnt0, *cnt1;
    cudaGetSymbolAddress((void**)&cnt0, g_cnt0);
    cudaGetSymbolAddress((void**)&cnt1, g_cnt1);

    float *xp3 = F+F_XP3, *xgp3 = F+F_XGP3;
    float *x1 = F+F_X1, *x2 = F+F_X2, *x3 = F+F_X3;
    float *x1g = F+F_X1G, *x2g = F+F_X2G, *x3g = F+F_X3G;
    float *P = F+F_P, *R = F+F_R, *Q = F+F_Q, *gn = F+F_GNRM, *maxb = F+F_MAXB;
    float *y7 = F+F_Y7, *y8 = F+F_Y8;
    float2 *W6P = (float2*)(F+F_W6P), *W7P = (float2*)(F+F_W7P);
    float2 *W8P = (float2*)(F+F_W8P), *W9P = (float2*)(F+F_W9P);
    float *W2T = F+F_W2T, *W4T = F+F_W4T, *c7 = F+F_C7;
    float *sc0 = F+F_SC0, *bi0 = F+F_BI0, *sc1 = F+F_SC1, *bi1 = F+F_BI1;
    float *QS = F+F_QS, *QS2 = F+F_QS2, *QM = F+F_QM;

    k_setup<<<96, 256>>>(x, xg, W[1], W[3], W[5], W[6], W[7], W[8],
                         xp3, xgp3, W2T, W4T, W6P, W7P, W8P, W9P);

    int graph3_blocks = NB*MM/4 + 512;
    int graph64_blocks = NB*MM/4 + 256;
    int xg_blocks = (NB*NN*64 + NB*MM*64)/256;
    int prep_blocks = NB*NN*64/256 + NB*MM*64/256 + 4;

    // ---- stage 1 (C=3) ----
    k_stageprep<3><<<prep_blocks, 256>>>(xp3, xgp3, W[0], P, R, Q, gn);
    k_graph<3><<<graph3_blocks, 128>>>(xp3, xgp3, gn, Q, QS, QS2, QM, near0);
    k_ptstats<<<NB*NN/32, 256>>>(P, R, QS, QS2, near0, D+0, D+64, cnt0, 1);
    k_scanbn<<<2, 1024>>>(cnt0, D+0, D+64, ga[0], ba[0], sc0, bi0);
    k_scatter<<<NB*NN/256, 256>>>(near0);
    k_convb<<<2*NB*MM, 128>>>(P, R, Q, W2T, sc0, bi0, cnt0, maxb, D+128, D+192);
    k_bnparams<<<1, 512>>>(D+128, D+192, ga[1], ba[1], 64, 409600.0, sc1, bi1);
    k_xg<<<xg_blocks, 256>>>(maxb, sc1, bi1, FPS, x1, x1g);

    // ---- stage 2 (C=64) ----
    k_stageprep<64><<<prep_blocks, 256>>>(x1, x1g, W[2], P, R, Q, gn);
    k_graph<64><<<graph64_blocks, 128>>>(x1, x1g, gn, Q, QS, QS2, QM, near1);
    k_ptstats<<<NB*NN/32, 256>>>(P, R, QS, QS2, near1, D+256, D+320, cnt1, 1);
    k_scanbn<<<2, 1024>>>(cnt1, D+256, D+320, ga[2], ba[2], sc0, bi0);
    k_scatter<<<NB*NN/256, 256>>>(near1);
    k_convb<<<2*NB*MM, 128>>>(P, R, Q, W4T, sc0, bi0, cnt1, maxb, D+384, D+448);
    k_bnparams<<<1, 512>>>(D+384, D+448, ga[3], ba[3], 64, 409600.0, sc1, bi1);
    k_xg<<<xg_blocks, 256>>>(maxb, sc1, bi1, FPS, x2, x2g);

    // ---- stage 3 (C=64, W5 only) ----
    k_stageprep<64><<<prep_blocks, 256>>>(x2, x2g, W[4], P, R, Q, gn);
    k_graph<64><<<graph64_blocks, 128>>>(x2, x2g, gn, Q, QS, QS2, QM, near2);
    k_ptstats<<<NB*NN/32, 256>>>(P, R, QS, QS2, near2, D+512, D+576, cnt1, 0);
    k_bnparams<<<1, 512>>>(D+512, D+576, ga[4], ba[4], 64, 409600.0, sc0, bi0);
    k_x3g<<<xg_blocks, 256>>>(P, R, QM, near2, sc0, bi0, FPS, x3, x3g);

    // ---- tail ----
    k_y6stats<<<dim3(NB*MM/16, 4), 128>>>(x1g, x2g, x3g, W6P, D+640, D+1152);
    k_bnparams<<<1, 512>>>(D+640, D+1152, ga[5], ba[5], 512, 1024.0, sc0, bi0);
    k_c7<<<1, 256>>>(W[6], sc0, bi0, c7);
    k_y7<<<NB*NN/16, 128>>>(x1, x2, x3, W7P, c7, y7, D+1664, D+1792);
    k_bnparams<<<1, 512>>>(D+1664, D+1792, ga[6], ba[6], 128, 8192.0, sc1, bi1);
    k_y8<<<NB*NN/16, 64>>>(y7, W8P, sc1, bi1, y8, D+1920, D+1984);
    k_bnparams<<<1, 512>>>(D+1920, D+1984, ga[7], ba[7], 64, 8192.0, sc0, bi0);
    k_out<<<NB*NN/16, 128>>>(y8, W9P, sc0, bi0, out);
}